// round 1
// baseline (speedup 1.0000x reference)
#include <cuda_runtime.h>

typedef unsigned long long ull;

#define NTOK 48
#define DM   128
#define NPAIR 64
#define TS   132           // padded row stride for tgt / weff / S2
#define SS   49            // padded row stride for scores/attn
#define SMEM_FLOATS (NTOK*TS + NPAIR*TS + NPAIR*SS)   // 6336 + 8448 + 3136 = 17920
#define SMEM_BYTES  (SMEM_FLOATS * 4)                 // 71680

// ---------------- device-global precomputed tensors (written every launch) --------
__device__ __align__(16) float g_weff[NPAIR * DM];      // folded 0.25 * q0 . Wk per (row,head)
__device__ __align__(16) float g_WvT [DM * DM];
__device__ __align__(16) float g_WpT [DM * DM];
__device__ __align__(16) float g_Wf1T[DM * DM];
__device__ __align__(16) float g_Wf2T[DM * DM];

// ---------------- packed fp32x2 helpers ----------------
__device__ __forceinline__ void ffma2(ull& d, ull a, ull b) {
    asm("fma.rn.f32x2 %0, %1, %2, %0;" : "+l"(d) : "l"(a), "l"(b));
}
__device__ __forceinline__ ull dup2(float x) {
    ull r; asm("mov.b64 %0, {%1, %1};" : "=l"(r) : "f"(x)); return r;
}
__device__ __forceinline__ void unpack2(ull v, float& lo, float& hi) {
    asm("mov.b64 {%0, %1}, %2;" : "=f"(lo), "=f"(hi) : "l"(v));
}
__device__ __forceinline__ float hsum2(ull v) {
    float lo, hi; unpack2(v, lo, hi); return lo + hi;
}

// =====================================================================
// Prologue: LN(query) -> q0 -> w_eff ; transpose the big weights.
// Tiny (1 block), batch-independent.
// =====================================================================
__global__ void k_pre(const float* __restrict__ q, const float* __restrict__ g1,
                      const float* __restrict__ b1, const float* __restrict__ Wq,
                      const float* __restrict__ bq, const float* __restrict__ Wk,
                      const float* __restrict__ Wv, const float* __restrict__ Wp,
                      const float* __restrict__ Wf1, const float* __restrict__ Wf2)
{
    __shared__ float qn[8][DM];
    __shared__ float q0[8][DM];
    const int tid = threadIdx.x;

    if (tid < 8) {
        float m = 0.f;
        for (int t = 0; t < DM; t++) m += q[tid*DM + t];
        m *= (1.f/DM);
        float v = 0.f;
        for (int t = 0; t < DM; t++) { float d = q[tid*DM + t] - m; v += d*d; }
        v *= (1.f/DM);
        float rs = rsqrtf(v + 1e-5f);
        for (int t = 0; t < DM; t++)
            qn[tid][t] = (q[tid*DM + t] - m) * rs * g1[t] + b1[t];
    }
    __syncthreads();

    for (int o = tid; o < 8*DM; o += blockDim.x) {
        int r = o >> 7, c = o & 127;
        float a = bq[c];
        for (int t = 0; t < DM; t++) a += qn[r][t] * Wq[c*DM + t];
        q0[r][c] = a;
    }
    __syncthreads();

    for (int o = tid; o < NPAIR*DM; o += blockDim.x) {
        int p = o >> 7, t = o & 127;
        int r = p >> 3, h = p & 7;
        float a = 0.f;
        #pragma unroll
        for (int d = 0; d < 16; d++)
            a += q0[r][h*16 + d] * Wk[(h*16 + d)*DM + t];
        g_weff[o] = 0.25f * a;       // scale = (d_head=16)^-0.5
    }

    for (int o = tid; o < DM*DM; o += blockDim.x) {
        int dd = o >> 7, c = o & 127;
        g_WvT [o] = Wv [c*DM + dd];
        g_WpT [o] = Wp [c*DM + dd];
        g_Wf1T[o] = Wf1[c*DM + dd];
        g_Wf2T[o] = Wf2[c*DM + dd];
    }
}

// =====================================================================
// Main: one CTA per batch element, 256 threads.
// =====================================================================
__global__ __launch_bounds__(256)
void k_main(const float* __restrict__ tgt, const float* __restrict__ query,
            const float* __restrict__ bv,  const float* __restrict__ bp,
            const float* __restrict__ g2,  const float* __restrict__ b2,
            const float* __restrict__ bf1, const float* __restrict__ bf2,
            float* __restrict__ out)
{
    extern __shared__ float sm[];
    float* s_tgt  = sm;                       // [48*132]  phases 1-4
    float* s_x    = sm;                       // [8*132]   overlay, phases 6+
    float* s_xn   = sm + 1056;                // [8*132]
    float* s_h    = sm + 2112;                // [8*132]
    float* s_w    = sm + NTOK*TS;             // weff (ph2) then S2 (ph4-5) [64*132]
    float* s_P    = sm + NTOK*TS + NPAIR*TS;  // scores->attn [64*49] phases 2-4
    float* s_xatt = s_P;                      // [8*132] overlay, phases 5-6

    const int tid = threadIdx.x;
    const int b   = blockIdx.x;
    const float* tb = tgt + (size_t)b * (NTOK*DM);

    // -------- Phase 1: stage tgt[b] and w_eff into smem --------
    {
        const float4* t4 = (const float4*)tb;
        for (int i = tid; i < NTOK*DM/4; i += 256) {
            float4 v = t4[i];
            int r = i >> 5, c = (i & 31) << 2;
            *(float4*)(s_tgt + r*TS + c) = v;
        }
        for (int i = tid; i < NPAIR*DM/4; i += 256) {
            float4 v = *(const float4*)(g_weff + i*4);
            int p = i >> 5, c = (i & 31) << 2;
            *(float4*)(s_w + p*TS + c) = v;
        }
    }
    __syncthreads();

    // -------- Phase 2: scores S[64][48] = weff . tgt  (4 pairs x 3 tokens / thread)
    {
        const int pt = (tid >> 4) * 4;
        const int jt = (tid & 15) * 3;
        const ulonglong2* w0 = (const ulonglong2*)(s_w + (pt+0)*TS);
        const ulonglong2* w1 = (const ulonglong2*)(s_w + (pt+1)*TS);
        const ulonglong2* w2 = (const ulonglong2*)(s_w + (pt+2)*TS);
        const ulonglong2* w3 = (const ulonglong2*)(s_w + (pt+3)*TS);
        const ulonglong2* t0 = (const ulonglong2*)(s_tgt + (jt+0)*TS);
        const ulonglong2* t1 = (const ulonglong2*)(s_tgt + (jt+1)*TS);
        const ulonglong2* t2 = (const ulonglong2*)(s_tgt + (jt+2)*TS);
        ull acc[4][3];
        #pragma unroll
        for (int a = 0; a < 4; a++)
            #pragma unroll
            for (int c = 0; c < 3; c++) acc[a][c] = 0ull;
        #pragma unroll 4
        for (int d = 0; d < DM/4; d++) {
            ulonglong2 a0 = w0[d], a1 = w1[d], a2 = w2[d], a3 = w3[d];
            ulonglong2 c0 = t0[d], c1 = t1[d], c2 = t2[d];
            ffma2(acc[0][0], a0.x, c0.x); ffma2(acc[0][0], a0.y, c0.y);
            ffma2(acc[0][1], a0.x, c1.x); ffma2(acc[0][1], a0.y, c1.y);
            ffma2(acc[0][2], a0.x, c2.x); ffma2(acc[0][2], a0.y, c2.y);
            ffma2(acc[1][0], a1.x, c0.x); ffma2(acc[1][0], a1.y, c0.y);
            ffma2(acc[1][1], a1.x, c1.x); ffma2(acc[1][1], a1.y, c1.y);
            ffma2(acc[1][2], a1.x, c2.x); ffma2(acc[1][2], a1.y, c2.y);
            ffma2(acc[2][0], a2.x, c0.x); ffma2(acc[2][0], a2.y, c0.y);
            ffma2(acc[2][1], a2.x, c1.x); ffma2(acc[2][1], a2.y, c1.y);
            ffma2(acc[2][2], a2.x, c2.x); ffma2(acc[2][2], a2.y, c2.y);
            ffma2(acc[3][0], a3.x, c0.x); ffma2(acc[3][0], a3.y, c0.y);
            ffma2(acc[3][1], a3.x, c1.x); ffma2(acc[3][1], a3.y, c1.y);
            ffma2(acc[3][2], a3.x, c2.x); ffma2(acc[3][2], a3.y, c2.y);
        }
        #pragma unroll
        for (int a = 0; a < 4; a++)
            #pragma unroll
            for (int c = 0; c < 3; c++)
                s_P[(pt+a)*SS + jt + c] = hsum2(acc[a][c]);
    }
    __syncthreads();

    // -------- Phase 3: masked softmax per pair (in place in s_P) --------
    if (tid < NPAIR) {
        const int p = tid, r = p >> 3;
        int h0 = 0, h1 = 8, w0 = 0, w1 = 6;
        if (r >= 2) {
            int wi = r - 2;
            h0 = (wi / 3) * 4; h1 = h0 + 4;
            w0 = (wi % 3) * 2; w1 = w0 + 2;
        }
        float* row = s_P + p*SS;
        float mx = -1e30f;
        for (int j = 0; j < NTOK; j++) {
            int hh = j / 6, ww = j - hh*6;
            if (hh >= h0 && hh < h1 && ww >= w0 && ww < w1)
                mx = fmaxf(mx, row[j]);
        }
        float sum = 0.f;
        for (int j = 0; j < NTOK; j++) {
            int hh = j / 6, ww = j - hh*6;
            if (hh >= h0 && hh < h1 && ww >= w0 && ww < w1) {
                float e = expf(row[j] - mx);
                row[j] = e; sum += e;
            } else row[j] = 0.f;
        }
        float inv = 1.f / sum;
        for (int j = 0; j < NTOK; j++) row[j] *= inv;
    }
    __syncthreads();

    // -------- Phase 4: S2[64][128] = P @ tgt (weighted token sums), overwrite weff
    {
        const int pt = (tid >> 4) * 4;
        const int ct = (tid & 15) * 8;
        ull acc[4][4];
        #pragma unroll
        for (int a = 0; a < 4; a++)
            #pragma unroll
            for (int c = 0; c < 4; c++) acc[a][c] = 0ull;
        const float* pr = s_P + pt*SS;
        for (int j = 0; j < NTOK; j++) {
            ull d0 = dup2(pr[j]);
            ull d1 = dup2(pr[SS + j]);
            ull d2 = dup2(pr[2*SS + j]);
            ull d3 = dup2(pr[3*SS + j]);
            const ulonglong2* tr = (const ulonglong2*)(s_tgt + j*TS + ct);
            ulonglong2 ta = tr[0], tc = tr[1];
            ffma2(acc[0][0], d0, ta.x); ffma2(acc[0][1], d0, ta.y);
            ffma2(acc[0][2], d0, tc.x); ffma2(acc[0][3], d0, tc.y);
            ffma2(acc[1][0], d1, ta.x); ffma2(acc[1][1], d1, ta.y);
            ffma2(acc[1][2], d1, tc.x); ffma2(acc[1][3], d1, tc.y);
            ffma2(acc[2][0], d2, ta.x); ffma2(acc[2][1], d2, ta.y);
            ffma2(acc[2][2], d2, tc.x); ffma2(acc[2][3], d2, tc.y);
            ffma2(acc[3][0], d3, ta.x); ffma2(acc[3][1], d3, ta.y);
            ffma2(acc[3][2], d3, tc.x); ffma2(acc[3][3], d3, tc.y);
        }
        #pragma unroll
        for (int a = 0; a < 4; a++) {
            ull* o = (ull*)(s_w + (pt+a)*TS + ct);
            o[0] = acc[a][0]; o[1] = acc[a][1]; o[2] = acc[a][2]; o[3] = acc[a][3];
        }
    }
    __syncthreads();

    // -------- Phase 5: x_att[r][h*16+i] = Wv_h @ S2[p] + bv (head slice) --------
    {
        const int p = tid >> 2;
        const int r = p >> 3, h = p & 7;
        const int col = h*16 + (tid & 3)*4;
        const float* s2 = s_w + p*TS;
        ull a01 = 0ull, a23 = 0ull;
        #pragma unroll 4
        for (int t = 0; t < DM; t++) {
            ull sv = dup2(s2[t]);
            ulonglong2 w = *(const ulonglong2*)(g_WvT + t*DM + col);
            ffma2(a01, sv, w.x); ffma2(a23, sv, w.y);
        }
        float o0, o1, o2, o3;
        unpack2(a01, o0, o1); unpack2(a23, o2, o3);
        s_xatt[r*TS + col + 0] = o0 + bv[col + 0];
        s_xatt[r*TS + col + 1] = o1 + bv[col + 1];
        s_xatt[r*TS + col + 2] = o2 + bv[col + 2];
        s_xatt[r*TS + col + 3] = o3 + bv[col + 3];
    }
    __syncthreads();

    // -------- Phase 6: x = query + x_att @ Wp^T + bp  (warp per row) --------
    {
        const int r = tid >> 5;
        const int col = (tid & 31) * 4;
        const float* xa = s_xatt + r*TS;
        ull a01 = 0ull, a23 = 0ull;
        #pragma unroll 4
        for (int d = 0; d < DM; d++) {
            ull xd = dup2(xa[d]);
            ulonglong2 w = *(const ulonglong2*)(g_WpT + d*DM + col);
            ffma2(a01, xd, w.x); ffma2(a23, xd, w.y);
        }
        float o0, o1, o2, o3;
        unpack2(a01, o0, o1); unpack2(a23, o2, o3);
        s_x[r*TS + col + 0] = query[r*DM + col + 0] + bp[col + 0] + o0;
        s_x[r*TS + col + 1] = query[r*DM + col + 1] + bp[col + 1] + o1;
        s_x[r*TS + col + 2] = query[r*DM + col + 2] + bp[col + 2] + o2;
        s_x[r*TS + col + 3] = query[r*DM + col + 3] + bp[col + 3] + o3;
    }
    __syncthreads();

    // -------- Phase 7: LayerNorm (warp per row) --------
    {
        const int r = tid >> 5;
        const int col = (tid & 31) * 4;
        float v0 = s_x[r*TS + col + 0], v1 = s_x[r*TS + col + 1];
        float v2 = s_x[r*TS + col + 2], v3 = s_x[r*TS + col + 3];
        float sum = v0 + v1 + v2 + v3;
        float sq  = v0*v0 + v1*v1 + v2*v2 + v3*v3;
        #pragma unroll
        for (int o = 16; o > 0; o >>= 1) {
            sum += __shfl_xor_sync(0xffffffffu, sum, o);
            sq  += __shfl_xor_sync(0xffffffffu, sq,  o);
        }
        float m  = sum * (1.f/DM);
        float var = sq * (1.f/DM) - m*m;
        float rs = rsqrtf(var + 1e-5f);
        s_xn[r*TS + col + 0] = (v0 - m) * rs * g2[col + 0] + b2[col + 0];
        s_xn[r*TS + col + 1] = (v1 - m) * rs * g2[col + 1] + b2[col + 1];
        s_xn[r*TS + col + 2] = (v2 - m) * rs * g2[col + 2] + b2[col + 2];
        s_xn[r*TS + col + 3] = (v3 - m) * rs * g2[col + 3] + b2[col + 3];
    }
    __syncthreads();

    // -------- Phase 8: h = gelu(xn @ Wf1^T + bf1), exact erf --------
    {
        const int r = tid >> 5;
        const int col = (tid & 31) * 4;
        const float* xn = s_xn + r*TS;
        ull a01 = 0ull, a23 = 0ull;
        #pragma unroll 4
        for (int d = 0; d < DM; d++) {
            ull xd = dup2(xn[d]);
            ulonglong2 w = *(const ulonglong2*)(g_Wf1T + d*DM + col);
            ffma2(a01, xd, w.x); ffma2(a23, xd, w.y);
        }
        float o[4];
        unpack2(a01, o[0], o[1]); unpack2(a23, o[2], o[3]);
        #pragma unroll
        for (int k = 0; k < 4; k++) {
            float z = o[k] + bf1[col + k];
            s_h[r*TS + col + k] = 0.5f * z * (1.f + erff(z * 0.7071067811865476f));
        }
    }
    __syncthreads();

    // -------- Phase 9: out = x + h @ Wf2^T + bf2 --------
    {
        const int r = tid >> 5;
        const int col = (tid & 31) * 4;
        const float* hh = s_h + r*TS;
        ull a01 = 0ull, a23 = 0ull;
        #pragma unroll 4
        for (int d = 0; d < DM; d++) {
            ull xd = dup2(hh[d]);
            ulonglong2 w = *(const ulonglong2*)(g_Wf2T + d*DM + col);
            ffma2(a01, xd, w.x); ffma2(a23, xd, w.y);
        }
        float o0, o1, o2, o3;
        unpack2(a01, o0, o1); unpack2(a23, o2, o3);
        float4 res;
        res.x = s_x[r*TS + col + 0] + bf2[col + 0] + o0;
        res.y = s_x[r*TS + col + 1] + bf2[col + 1] + o1;
        res.z = s_x[r*TS + col + 2] + bf2[col + 2] + o2;
        res.w = s_x[r*TS + col + 3] + bf2[col + 3] + o3;
        *(float4*)(out + (size_t)b*(8*DM) + r*DM + col) = res;
    }
}

// =====================================================================
extern "C" void kernel_launch(void* const* d_in, const int* in_sizes, int n_in,
                              void* d_out, int out_size)
{
    const float* query = (const float*)d_in[0];
    const float* tgt   = (const float*)d_in[1];
    const float* g1    = (const float*)d_in[2];
    const float* b1    = (const float*)d_in[3];
    const float* Wq    = (const float*)d_in[4];
    const float* bq    = (const float*)d_in[5];
    const float* Wk    = (const float*)d_in[6];
    // d_in[7] = bk: provably drops out (uniform shift per softmax row)
    const float* Wv    = (const float*)d_in[8];
    const float* bv    = (const float*)d_in[9];
    const float* Wp    = (const float*)d_in[10];
    const float* bp    = (const float*)d_in[11];
    const float* g2    = (const float*)d_in[12];
    const float* b2    = (const float*)d_in[13];
    const float* Wf1   = (const float*)d_in[14];
    const float* bf1   = (const float*)d_in[15];
    const float* Wf2   = (const float*)d_in[16];
    const float* bf2   = (const float*)d_in[17];

    const int B = in_sizes[1] / (NTOK * DM);

    cudaFuncSetAttribute(k_main, cudaFuncAttributeMaxDynamicSharedMemorySize, SMEM_BYTES);

    k_pre<<<1, 256>>>(query, g1, b1, Wq, bq, Wk, Wv, Wp, Wf1, Wf2);
    k_main<<<B, 256, SMEM_BYTES>>>(tgt, query, bv, bp, g2, b2, bf1, bf2, (float*)d_out);
}

// round 2
// speedup vs baseline: 1.0449x; 1.0449x over previous
#include <cuda_runtime.h>

typedef unsigned long long ull;

#define NTOK 48
#define DM   128
#define TS   132           // padded row stride for tgt (and x/xn/h/xatt overlays)
#define SS   49            // padded row stride for scores/attn
#define S2S  132           // S2 row stride

// smem float offsets
#define SM_TGT  0                      // [48*132] = 6336
#define SM_P    6336                   // [64*49]  = 3136
#define SM_S2   (6336+3136)            // [64*132] = 8448
#define SMEM_FLOATS 17920
#define SMEM_BYTES  (SMEM_FLOATS*4)    // 71680
// overlays into tgt region (free after phase 4)
#define SM_XATT 0
#define SM_X    1056
#define SM_XN   2112
#define SM_H    3168

// ---------------- device-global precomputed tensors --------
__device__ __align__(16) float g_weff[64 * DM];     // 0.25 * q0 . Wk per (row,head)
__device__ __align__(16) float g_WvT [DM * DM];
__device__ __align__(16) float g_WpT [DM * DM];
__device__ __align__(16) float g_Wf1T[DM * DM];
__device__ __align__(16) float g_Wf2T[DM * DM];

// ---------------- packed fp32x2 helpers ----------------
__device__ __forceinline__ void ffma2(ull& d, ull a, ull b) {
    asm("fma.rn.f32x2 %0, %1, %2, %0;" : "+l"(d) : "l"(a), "l"(b));
}
__device__ __forceinline__ ull dup2(float x) {
    ull r; asm("mov.b64 %0, {%1, %1};" : "=l"(r) : "f"(x)); return r;
}
__device__ __forceinline__ void unpack2(ull v, float& lo, float& hi) {
    asm("mov.b64 {%0, %1}, %2;" : "=f"(lo), "=f"(hi) : "l"(v));
}
__device__ __forceinline__ float hsum2(ull v) {
    float lo, hi; unpack2(v, lo, hi); return lo + hi;
}

// =====================================================================
// Prologue (1 block): LN(query) -> q0 -> w_eff ; transpose big weights.
// =====================================================================
__global__ void k_pre(const float* __restrict__ q, const float* __restrict__ g1,
                      const float* __restrict__ b1, const float* __restrict__ Wq,
                      const float* __restrict__ bq, const float* __restrict__ Wk,
                      const float* __restrict__ Wv, const float* __restrict__ Wp,
                      const float* __restrict__ Wf1, const float* __restrict__ Wf2)
{
    __shared__ float qn[8][DM];
    __shared__ float q0[8][DM];
    const int tid = threadIdx.x;

    if (tid < 8) {
        float m = 0.f;
        for (int t = 0; t < DM; t++) m += q[tid*DM + t];
        m *= (1.f/DM);
        float v = 0.f;
        for (int t = 0; t < DM; t++) { float d = q[tid*DM + t] - m; v += d*d; }
        v *= (1.f/DM);
        float rs = rsqrtf(v + 1e-5f);
        for (int t = 0; t < DM; t++)
            qn[tid][t] = (q[tid*DM + t] - m) * rs * g1[t] + b1[t];
    }
    __syncthreads();

    for (int o = tid; o < 8*DM; o += blockDim.x) {
        int r = o >> 7, c = o & 127;
        float a = bq[c];
        for (int t = 0; t < DM; t++) a += qn[r][t] * Wq[c*DM + t];
        q0[r][c] = a;
    }
    __syncthreads();

    for (int o = tid; o < 64*DM; o += blockDim.x) {
        int p = o >> 7, t = o & 127;
        int r = p >> 3, h = p & 7;
        float a = 0.f;
        #pragma unroll
        for (int d = 0; d < 16; d++)
            a += q0[r][h*16 + d] * Wk[(h*16 + d)*DM + t];
        g_weff[o] = 0.25f * a;       // scale = (d_head=16)^-0.5
    }

    for (int o = tid; o < DM*DM; o += blockDim.x) {
        int dd = o >> 7, c = o & 127;
        g_WvT [o] = Wv [c*DM + dd];
        g_WpT [o] = Wp [c*DM + dd];
        g_Wf1T[o] = Wf1[c*DM + dd];
        g_Wf2T[o] = Wf2[c*DM + dd];
    }
}

// =====================================================================
// Main: one CTA per batch element, 256 threads, 3 CTAs/SM.
// =====================================================================
__global__ __launch_bounds__(256, 3)
void k_main(const float* __restrict__ tgt, const float* __restrict__ query,
            const float* __restrict__ bv,  const float* __restrict__ bp,
            const float* __restrict__ g2,  const float* __restrict__ b2,
            const float* __restrict__ bf1, const float* __restrict__ bf2,
            float* __restrict__ out)
{
    extern __shared__ float sm[];
    const int tid = threadIdx.x;
    const int b   = blockIdx.x;

    // -------- Phase 1: stage tgt[b] into smem (padded rows) --------
    {
        const float4* t4 = (const float4*)(tgt + (size_t)b * (NTOK*DM));
        #pragma unroll
        for (int k = 0; k < 6; k++) {
            int i = tid + k*256;
            float4 v = t4[i];
            int r = i >> 5, c = (i & 31) << 2;
            *(float4*)(sm + SM_TGT + r*TS + c) = v;
        }
    }
    __syncthreads();

    // -------- Phase 2: scores (windowed) --------
    if (tid < 128) {
        // Group A: pairs 0..15 (full 48 tokens). tile = 2 pairs x 3 tokens.
        const int pa = (tid >> 4) * 2;       // 0..14
        const int jt = (tid & 15) * 3;       // 0..45
        const ulonglong2* w0 = (const ulonglong2*)(g_weff + pa*DM);
        const ulonglong2* w1 = (const ulonglong2*)(g_weff + (pa+1)*DM);
        const ulonglong2* t0 = (const ulonglong2*)(sm + SM_TGT + (jt+0)*TS);
        const ulonglong2* t1 = (const ulonglong2*)(sm + SM_TGT + (jt+1)*TS);
        const ulonglong2* t2 = (const ulonglong2*)(sm + SM_TGT + (jt+2)*TS);
        ull acc[2][3] = {};
        #pragma unroll 4
        for (int d = 0; d < 32; d++) {
            ulonglong2 a0 = w0[d], a1 = w1[d];
            ulonglong2 c0 = t0[d], c1 = t1[d], c2 = t2[d];
            ffma2(acc[0][0], a0.x, c0.x); ffma2(acc[0][0], a0.y, c0.y);
            ffma2(acc[0][1], a0.x, c1.x); ffma2(acc[0][1], a0.y, c1.y);
            ffma2(acc[0][2], a0.x, c2.x); ffma2(acc[0][2], a0.y, c2.y);
            ffma2(acc[1][0], a1.x, c0.x); ffma2(acc[1][0], a1.y, c0.y);
            ffma2(acc[1][1], a1.x, c1.x); ffma2(acc[1][1], a1.y, c1.y);
            ffma2(acc[1][2], a1.x, c2.x); ffma2(acc[1][2], a1.y, c2.y);
        }
        #pragma unroll
        for (int a = 0; a < 2; a++)
            #pragma unroll
            for (int c = 0; c < 3; c++)
                sm[SM_P + (pa+a)*SS + jt + c] = hsum2(acc[a][c]);
    } else if (tid < 224) {
        // Group B: pairs 16..63, 8 window tokens each (stored compactly at m=0..7)
        const int t2i = tid - 128;            // 0..95
        const int p   = 16 + (t2i >> 2) * 2;  // even pair; p,p+1 share r (p even)
        const int mg  = t2i & 3;              // token pair m0=2mg, m0+1
        const int r   = p >> 3, wi = r - 2;
        const int hw  = (wi/3)*4, ww = (wi%3)*2;
        const int m0  = mg*2;
        const int j0  = (hw + mg)*6 + ww;     // tokens j0, j0+1 (adjacent cols)
        const ulonglong2* w0 = (const ulonglong2*)(g_weff + p*DM);
        const ulonglong2* w1 = (const ulonglong2*)(g_weff + (p+1)*DM);
        const ulonglong2* t0 = (const ulonglong2*)(sm + SM_TGT + (j0+0)*TS);
        const ulonglong2* t1 = (const ulonglong2*)(sm + SM_TGT + (j0+1)*TS);
        ull acc[2][2] = {};
        #pragma unroll 4
        for (int d = 0; d < 32; d++) {
            ulonglong2 a0 = w0[d], a1 = w1[d];
            ulonglong2 c0 = t0[d], c1 = t1[d];
            ffma2(acc[0][0], a0.x, c0.x); ffma2(acc[0][0], a0.y, c0.y);
            ffma2(acc[0][1], a0.x, c1.x); ffma2(acc[0][1], a0.y, c1.y);
            ffma2(acc[1][0], a1.x, c0.x); ffma2(acc[1][0], a1.y, c0.y);
            ffma2(acc[1][1], a1.x, c1.x); ffma2(acc[1][1], a1.y, c1.y);
        }
        sm[SM_P + p*SS     + m0    ] = hsum2(acc[0][0]);
        sm[SM_P + p*SS     + m0 + 1] = hsum2(acc[0][1]);
        sm[SM_P + (p+1)*SS + m0    ] = hsum2(acc[1][0]);
        sm[SM_P + (p+1)*SS + m0 + 1] = hsum2(acc[1][1]);
    }
    __syncthreads();

    // -------- Phase 3: softmax per pair (compact rows; no masking needed) --------
    if (tid < 64) {
        const int n = (tid < 16) ? 48 : 8;
        float* row = sm + SM_P + tid*SS;
        float mx = -1e30f;
        for (int j = 0; j < n; j++) mx = fmaxf(mx, row[j]);
        float sum = 0.f;
        for (int j = 0; j < n; j++) { float e = expf(row[j] - mx); row[j] = e; sum += e; }
        float inv = 1.f / sum;
        for (int j = 0; j < n; j++) row[j] *= inv;
    }
    __syncthreads();

    // -------- Phase 4: S2 = P @ tgt (windowed weighted token sums) --------
    if (tid < 128) {
        // Group A: pairs 0..15, 48 tokens. thread = (pair, 16-col chunk)
        const int pi = tid >> 3;             // 0..15
        const int ch = (tid & 7) * 16;       // col base
        ull acc[8] = {};
        const float* pr = sm + SM_P + pi*SS;
        for (int j = 0; j < 48; j++) {
            ull pj = dup2(pr[j]);
            const ulonglong2* tr = (const ulonglong2*)(sm + SM_TGT + j*TS + ch);
            ulonglong2 u0 = tr[0], u1 = tr[1], u2 = tr[2], u3 = tr[3];
            ffma2(acc[0], pj, u0.x); ffma2(acc[1], pj, u0.y);
            ffma2(acc[2], pj, u1.x); ffma2(acc[3], pj, u1.y);
            ffma2(acc[4], pj, u2.x); ffma2(acc[5], pj, u2.y);
            ffma2(acc[6], pj, u3.x); ffma2(acc[7], pj, u3.y);
        }
        ull* o = (ull*)(sm + SM_S2 + pi*S2S + ch);
        #pragma unroll
        for (int k = 0; k < 8; k++) o[k] = acc[k];
    } else {
        // Group B: pairs 16..63, 8 window tokens. 3 sweeps of (16 pairs x 8 chunks)
        const int t2i = tid - 128;
        #pragma unroll
        for (int u = 0; u < 3; u++) {
            const int p  = 16 + u*16 + (t2i >> 3);
            const int ch = (t2i & 7) * 16;
            const int r  = p >> 3, wi = r - 2;
            const int hw = (wi/3)*4, ww = (wi%3)*2;
            ull acc[8] = {};
            const float* pr = sm + SM_P + p*SS;
            #pragma unroll
            for (int m = 0; m < 8; m++) {
                const int j = (hw + (m>>1))*6 + ww + (m&1);
                ull pj = dup2(pr[m]);
                const ulonglong2* tr = (const ulonglong2*)(sm + SM_TGT + j*TS + ch);
                ulonglong2 u0 = tr[0], u1 = tr[1], u2 = tr[2], u3 = tr[3];
                ffma2(acc[0], pj, u0.x); ffma2(acc[1], pj, u0.y);
                ffma2(acc[2], pj, u1.x); ffma2(acc[3], pj, u1.y);
                ffma2(acc[4], pj, u2.x); ffma2(acc[5], pj, u2.y);
                ffma2(acc[6], pj, u3.x); ffma2(acc[7], pj, u3.y);
            }
            ull* o = (ull*)(sm + SM_S2 + p*S2S + ch);
            #pragma unroll
            for (int k = 0; k < 8; k++) o[k] = acc[k];
        }
    }
    __syncthreads();

    // -------- Phase 5: x_att[r][c] = (Wv_h @ S2[r*8+h])[c] + bv[c]
    // thread owns col-pair; 4 rows each; weight row read once per d CTA-wide.
    if (tid < 128) {
        const int c2  = tid & 63;
        const int rg  = tid >> 6;            // rows rg*4 .. rg*4+3
        const int h   = c2 >> 3;
        const int col = c2 * 2;
        ull acc[4] = {};
        for (int t4 = 0; t4 < 32; t4++) {
            ull wv0 = *(const ull*)(g_WvT + (t4*4+0)*DM + col);
            ull wv1 = *(const ull*)(g_WvT + (t4*4+1)*DM + col);
            ull wv2 = *(const ull*)(g_WvT + (t4*4+2)*DM + col);
            ull wv3 = *(const ull*)(g_WvT + (t4*4+3)*DM + col);
            #pragma unroll
            for (int ri = 0; ri < 4; ri++) {
                const int row = (rg*4+ri)*8 + h;
                float4 s4 = *(const float4*)(sm + SM_S2 + row*S2S + t4*4);
                ffma2(acc[ri], dup2(s4.x), wv0);
                ffma2(acc[ri], dup2(s4.y), wv1);
                ffma2(acc[ri], dup2(s4.z), wv2);
                ffma2(acc[ri], dup2(s4.w), wv3);
            }
        }
        #pragma unroll
        for (int ri = 0; ri < 4; ri++) {
            float lo, hi; unpack2(acc[ri], lo, hi);
            const int r = rg*4+ri;
            sm[SM_XATT + r*TS + col    ] = lo + bv[col];
            sm[SM_XATT + r*TS + col + 1] = hi + bv[col + 1];
        }
    }
    __syncthreads();

    // -------- Phase 6: x = query + x_att @ Wp^T + bp --------
    if (tid < 128) {
        const int c2  = tid & 63;
        const int rg  = tid >> 6;
        const int col = c2 * 2;
        ull acc[4] = {};
        for (int d4 = 0; d4 < 32; d4++) {
            ull w0 = *(const ull*)(g_WpT + (d4*4+0)*DM + col);
            ull w1 = *(const ull*)(g_WpT + (d4*4+1)*DM + col);
            ull w2 = *(const ull*)(g_WpT + (d4*4+2)*DM + col);
            ull w3 = *(const ull*)(g_WpT + (d4*4+3)*DM + col);
            #pragma unroll
            for (int ri = 0; ri < 4; ri++) {
                const int r = rg*4+ri;
                float4 x4 = *(const float4*)(sm + SM_XATT + r*TS + d4*4);
                ffma2(acc[ri], dup2(x4.x), w0);
                ffma2(acc[ri], dup2(x4.y), w1);
                ffma2(acc[ri], dup2(x4.z), w2);
                ffma2(acc[ri], dup2(x4.w), w3);
            }
        }
        #pragma unroll
        for (int ri = 0; ri < 4; ri++) {
            float lo, hi; unpack2(acc[ri], lo, hi);
            const int r = rg*4+ri;
            sm[SM_X + r*TS + col    ] = query[r*DM + col    ] + bp[col    ] + lo;
            sm[SM_X + r*TS + col + 1] = query[r*DM + col + 1] + bp[col + 1] + hi;
        }
    }
    __syncthreads();

    // -------- Phase 7: LayerNorm (warp per row, all 8 warps) --------
    {
        const int r = tid >> 5;
        const int col = (tid & 31) * 4;
        float v0 = sm[SM_X + r*TS + col + 0], v1 = sm[SM_X + r*TS + col + 1];
        float v2 = sm[SM_X + r*TS + col + 2], v3 = sm[SM_X + r*TS + col + 3];
        float sum = v0 + v1 + v2 + v3;
        float sq  = v0*v0 + v1*v1 + v2*v2 + v3*v3;
        #pragma unroll
        for (int o = 16; o > 0; o >>= 1) {
            sum += __shfl_xor_sync(0xffffffffu, sum, o);
            sq  += __shfl_xor_sync(0xffffffffu, sq,  o);
        }
        float m   = sum * (1.f/DM);
        float var = sq * (1.f/DM) - m*m;
        float rs  = rsqrtf(var + 1e-5f);
        sm[SM_XN + r*TS + col + 0] = (v0 - m) * rs * g2[col + 0] + b2[col + 0];
        sm[SM_XN + r*TS + col + 1] = (v1 - m) * rs * g2[col + 1] + b2[col + 1];
        sm[SM_XN + r*TS + col + 2] = (v2 - m) * rs * g2[col + 2] + b2[col + 2];
        sm[SM_XN + r*TS + col + 3] = (v3 - m) * rs * g2[col + 3] + b2[col + 3];
    }
    __syncthreads();

    // -------- Phase 8: h = gelu(xn @ Wf1^T + bf1), exact erf --------
    if (tid < 128) {
        const int c2  = tid & 63;
        const int rg  = tid >> 6;
        const int col = c2 * 2;
        ull acc[4] = {};
        for (int d4 = 0; d4 < 32; d4++) {
            ull w0 = *(const ull*)(g_Wf1T + (d4*4+0)*DM + col);
            ull w1 = *(const ull*)(g_Wf1T + (d4*4+1)*DM + col);
            ull w2 = *(const ull*)(g_Wf1T + (d4*4+2)*DM + col);
            ull w3 = *(const ull*)(g_Wf1T + (d4*4+3)*DM + col);
            #pragma unroll
            for (int ri = 0; ri < 4; ri++) {
                const int r = rg*4+ri;
                float4 x4 = *(const float4*)(sm + SM_XN + r*TS + d4*4);
                ffma2(acc[ri], dup2(x4.x), w0);
                ffma2(acc[ri], dup2(x4.y), w1);
                ffma2(acc[ri], dup2(x4.z), w2);
                ffma2(acc[ri], dup2(x4.w), w3);
            }
        }
        #pragma unroll
        for (int ri = 0; ri < 4; ri++) {
            float lo, hi; unpack2(acc[ri], lo, hi);
            const int r = rg*4+ri;
            float z0 = lo + bf1[col];
            float z1 = hi + bf1[col + 1];
            sm[SM_H + r*TS + col    ] = 0.5f * z0 * (1.f + erff(z0 * 0.7071067811865476f));
            sm[SM_H + r*TS + col + 1] = 0.5f * z1 * (1.f + erff(z1 * 0.7071067811865476f));
        }
    }
    __syncthreads();

    // -------- Phase 9: out = x + h @ Wf2^T + bf2 --------
    if (tid < 128) {
        const int c2  = tid & 63;
        const int rg  = tid >> 6;
        const int col = c2 * 2;
        ull acc[4] = {};
        for (int d4 = 0; d4 < 32; d4++) {
            ull w0 = *(const ull*)(g_Wf2T + (d4*4+0)*DM + col);
            ull w1 = *(const ull*)(g_Wf2T + (d4*4+1)*DM + col);
            ull w2 = *(const ull*)(g_Wf2T + (d4*4+2)*DM + col);
            ull w3 = *(const ull*)(g_Wf2T + (d4*4+3)*DM + col);
            #pragma unroll
            for (int ri = 0; ri < 4; ri++) {
                const int r = rg*4+ri;
                float4 x4 = *(const float4*)(sm + SM_H + r*TS + d4*4);
                ffma2(acc[ri], dup2(x4.x), w0);
                ffma2(acc[ri], dup2(x4.y), w1);
                ffma2(acc[ri], dup2(x4.z), w2);
                ffma2(acc[ri], dup2(x4.w), w3);
            }
        }
        #pragma unroll
        for (int ri = 0; ri < 4; ri++) {
            float lo, hi; unpack2(acc[ri], lo, hi);
            const int r = rg*4+ri;
            float2 res;
            res.x = sm[SM_X + r*TS + col    ] + bf2[col    ] + lo;
            res.y = sm[SM_X + r*TS + col + 1] + bf2[col + 1] + hi;
            *(float2*)(out + (size_t)b*(8*DM) + r*DM + col) = res;
        }
    }
}

// =====================================================================
extern "C" void kernel_launch(void* const* d_in, const int* in_sizes, int n_in,
                              void* d_out, int out_size)
{
    const float* query = (const float*)d_in[0];
    const float* tgt   = (const float*)d_in[1];
    const float* g1    = (const float*)d_in[2];
    const float* b1    = (const float*)d_in[3];
    const float* Wq    = (const float*)d_in[4];
    const float* bq    = (const float*)d_in[5];
    const float* Wk    = (const float*)d_in[6];
    // d_in[7] = bk: drops out (uniform shift per softmax row)
    const float* Wv    = (const float*)d_in[8];
    const float* bv    = (const float*)d_in[9];
    const float* Wp    = (const float*)d_in[10];
    const float* bp    = (const float*)d_in[11];
    const float* g2    = (const float*)d_in[12];
    const float* b2    = (const float*)d_in[13];
    const float* Wf1   = (const float*)d_in[14];
    const float* bf1   = (const float*)d_in[15];
    const float* Wf2   = (const float*)d_in[16];
    const float* bf2   = (const float*)d_in[17];

    const int B = in_sizes[1] / (NTOK * DM);

    cudaFuncSetAttribute(k_main, cudaFuncAttributeMaxDynamicSharedMemorySize, SMEM_BYTES);

    k_pre<<<1, 256>>>(query, g1, b1, Wq, bq, Wk, Wv, Wp, Wf1, Wf2);
    k_main<<<B, 256, SMEM_BYTES>>>(tgt, query, bv, bp, g2, b2, bf1, bf2, (float*)d_out);
}

// round 3
// speedup vs baseline: 1.6609x; 1.5894x over previous
#include <cuda_runtime.h>

typedef unsigned long long ull;

#define NTOK 48
#define DM   128
#define TS   132
#define SS   49

// ---- kernel A smem (floats) ----
#define SM_TGT  0            // 48*132 = 6336
#define SM_P    6336         // 64*49  = 3136
#define SM_VP   9472         // 48*132 = 6336
#define A_SMEM_FLOATS 15808
#define A_SMEM_BYTES  (A_SMEM_FLOATS*4)   // 63232

// ---- kernel B smem (floats) ----
#define GB 8                 // batches per CTA
#define BROWS 64             // GB*8
#define SMB_XA  0            // 64*132 = 8448
#define SMB_X   8448         // 64*132
#define SMB_N   16896        // 64*132
#define SMB_W   25344        // 128*128 = 16384
#define SMB_Q   41728        // 8*128 = 1024
#define SMB_CB  42752        // 5*128 = 640 (bp,g2,b2,bf1,bf2)
#define B_SMEM_FLOATS 43392
#define B_SMEM_BYTES  (B_SMEM_FLOATS*4)   // 173568

#define MAXB 16384

// ---------------- device-global precomputed / scratch --------
__device__ __align__(16) float g_weff[64 * DM];
__device__ __align__(16) float g_WvT [DM * DM];
__device__ __align__(16) float g_WpT [DM * DM];
__device__ __align__(16) float g_Wf1T[DM * DM];
__device__ __align__(16) float g_Wf2T[DM * DM];
__device__ __align__(16) float g_xatt[(size_t)MAXB * 8 * DM];   // 64 MB scratch

// ---------------- packed fp32x2 helpers ----------------
__device__ __forceinline__ void ffma2(ull& d, ull a, ull b) {
    asm("fma.rn.f32x2 %0, %1, %2, %0;" : "+l"(d) : "l"(a), "l"(b));
}
__device__ __forceinline__ ull dup2(float x) {
    ull r; asm("mov.b64 %0, {%1, %1};" : "=l"(r) : "f"(x)); return r;
}
__device__ __forceinline__ void unpack2(ull v, float& lo, float& hi) {
    asm("mov.b64 {%0, %1}, %2;" : "=f"(lo), "=f"(hi) : "l"(v));
}
__device__ __forceinline__ float hsum2(ull v) {
    float lo, hi; unpack2(v, lo, hi); return lo + hi;
}

// =====================================================================
// Prologue (1 block): LN(query) -> q0 -> w_eff ; transpose big weights.
// =====================================================================
__global__ void k_pre(const float* __restrict__ q, const float* __restrict__ g1,
                      const float* __restrict__ b1, const float* __restrict__ Wq,
                      const float* __restrict__ bq, const float* __restrict__ Wk,
                      const float* __restrict__ Wv, const float* __restrict__ Wp,
                      const float* __restrict__ Wf1, const float* __restrict__ Wf2)
{
    __shared__ float qn[8][DM];
    __shared__ float q0[8][DM];
    const int tid = threadIdx.x;

    if (tid < 8) {
        float m = 0.f;
        for (int t = 0; t < DM; t++) m += q[tid*DM + t];
        m *= (1.f/DM);
        float v = 0.f;
        for (int t = 0; t < DM; t++) { float d = q[tid*DM + t] - m; v += d*d; }
        v *= (1.f/DM);
        float rs = rsqrtf(v + 1e-5f);
        for (int t = 0; t < DM; t++)
            qn[tid][t] = (q[tid*DM + t] - m) * rs * g1[t] + b1[t];
    }
    __syncthreads();

    for (int o = tid; o < 8*DM; o += blockDim.x) {
        int r = o >> 7, c = o & 127;
        float a = bq[c];
        for (int t = 0; t < DM; t++) a += qn[r][t] * Wq[c*DM + t];
        q0[r][c] = a;
    }
    __syncthreads();

    for (int o = tid; o < 64*DM; o += blockDim.x) {
        int p = o >> 7, t = o & 127;
        int r = p >> 3, h = p & 7;
        float a = 0.f;
        #pragma unroll
        for (int d = 0; d < 16; d++)
            a += q0[r][h*16 + d] * Wk[(h*16 + d)*DM + t];
        g_weff[o] = 0.25f * a;
    }

    for (int o = tid; o < DM*DM; o += blockDim.x) {
        int dd = o >> 7, c = o & 127;
        g_WvT [o] = Wv [c*DM + dd];
        g_WpT [o] = Wp [c*DM + dd];
        g_Wf1T[o] = Wf1[c*DM + dd];
        g_Wf2T[o] = Wf2[c*DM + dd];
    }
}

// =====================================================================
// Kernel A: one CTA per batch. scores -> softmax -> vproj -> x_att.
// =====================================================================
__global__ __launch_bounds__(256, 3)
void k_attn(const float* __restrict__ tgt, const float* __restrict__ bv)
{
    extern __shared__ float sm[];
    const int tid = threadIdx.x;
    const int b   = blockIdx.x;

    // -------- stage tgt[b] --------
    {
        const float4* t4 = (const float4*)(tgt + (size_t)b * (NTOK*DM));
        #pragma unroll
        for (int k = 0; k < 6; k++) {
            int i = tid + k*256;
            float4 v = t4[i];
            int r = i >> 5, c = (i & 31) << 2;
            *(float4*)(sm + SM_TGT + r*TS + c) = v;
        }
    }
    __syncthreads();

    // -------- scores (windowed) --------
    if (tid < 128) {
        const int pa = (tid >> 4) * 2;
        const int jt = (tid & 15) * 3;
        const ulonglong2* w0 = (const ulonglong2*)(g_weff + pa*DM);
        const ulonglong2* w1 = (const ulonglong2*)(g_weff + (pa+1)*DM);
        const ulonglong2* t0 = (const ulonglong2*)(sm + SM_TGT + (jt+0)*TS);
        const ulonglong2* t1 = (const ulonglong2*)(sm + SM_TGT + (jt+1)*TS);
        const ulonglong2* t2 = (const ulonglong2*)(sm + SM_TGT + (jt+2)*TS);
        ull acc[2][3] = {};
        #pragma unroll 4
        for (int d = 0; d < 32; d++) {
            ulonglong2 a0 = w0[d], a1 = w1[d];
            ulonglong2 c0 = t0[d], c1 = t1[d], c2 = t2[d];
            ffma2(acc[0][0], a0.x, c0.x); ffma2(acc[0][0], a0.y, c0.y);
            ffma2(acc[0][1], a0.x, c1.x); ffma2(acc[0][1], a0.y, c1.y);
            ffma2(acc[0][2], a0.x, c2.x); ffma2(acc[0][2], a0.y, c2.y);
            ffma2(acc[1][0], a1.x, c0.x); ffma2(acc[1][0], a1.y, c0.y);
            ffma2(acc[1][1], a1.x, c1.x); ffma2(acc[1][1], a1.y, c1.y);
            ffma2(acc[1][2], a1.x, c2.x); ffma2(acc[1][2], a1.y, c2.y);
        }
        #pragma unroll
        for (int a = 0; a < 2; a++)
            #pragma unroll
            for (int c = 0; c < 3; c++)
                sm[SM_P + (pa+a)*SS + jt + c] = hsum2(acc[a][c]);
    } else if (tid < 224) {
        const int t2i = tid - 128;
        const int p   = 16 + (t2i >> 2) * 2;
        const int mg  = t2i & 3;
        const int r   = p >> 3, wi = r - 2;
        const int hw  = (wi/3)*4, ww = (wi%3)*2;
        const int m0  = mg*2;
        const int j0  = (hw + mg)*6 + ww;
        const ulonglong2* w0 = (const ulonglong2*)(g_weff + p*DM);
        const ulonglong2* w1 = (const ulonglong2*)(g_weff + (p+1)*DM);
        const ulonglong2* t0 = (const ulonglong2*)(sm + SM_TGT + (j0+0)*TS);
        const ulonglong2* t1 = (const ulonglong2*)(sm + SM_TGT + (j0+1)*TS);
        ull acc[2][2] = {};
        #pragma unroll 4
        for (int d = 0; d < 32; d++) {
            ulonglong2 a0 = w0[d], a1 = w1[d];
            ulonglong2 c0 = t0[d], c1 = t1[d];
            ffma2(acc[0][0], a0.x, c0.x); ffma2(acc[0][0], a0.y, c0.y);
            ffma2(acc[0][1], a0.x, c1.x); ffma2(acc[0][1], a0.y, c1.y);
            ffma2(acc[1][0], a1.x, c0.x); ffma2(acc[1][0], a1.y, c0.y);
            ffma2(acc[1][1], a1.x, c1.x); ffma2(acc[1][1], a1.y, c1.y);
        }
        sm[SM_P + p*SS     + m0    ] = hsum2(acc[0][0]);
        sm[SM_P + p*SS     + m0 + 1] = hsum2(acc[0][1]);
        sm[SM_P + (p+1)*SS + m0    ] = hsum2(acc[1][0]);
        sm[SM_P + (p+1)*SS + m0 + 1] = hsum2(acc[1][1]);
    }
    __syncthreads();

    // -------- softmax per pair (compact rows) --------
    if (tid < 64) {
        const int n = (tid < 16) ? 48 : 8;
        float* row = sm + SM_P + tid*SS;
        float mx = -1e30f;
        for (int j = 0; j < n; j++) mx = fmaxf(mx, row[j]);
        float sum = 0.f;
        for (int j = 0; j < n; j++) { float e = expf(row[j] - mx); row[j] = e; sum += e; }
        float inv = 1.f / sum;
        for (int j = 0; j < n; j++) row[j] *= inv;
    }

    // -------- vproj[j] = tgt[j] @ WvT + bv  (48x128 @ 128x128) --------
    // 8 warps x 6 rows (warp-uniform -> A broadcast), 32 lanes x 4 cols.
    {
        const int w    = tid >> 5;
        const int lane = tid & 31;
        const int j0   = w * 6;
        const int col  = lane * 4;
        ull acc[6][2] = {};
        for (int k4 = 0; k4 < 32; k4++) {
            float4 a[6];
            #pragma unroll
            for (int r = 0; r < 6; r++)
                a[r] = *(const float4*)(sm + SM_TGT + (j0+r)*TS + k4*4);
            ulonglong2 b0 = *(const ulonglong2*)(g_WvT + (k4*4+0)*DM + col);
            ulonglong2 b1 = *(const ulonglong2*)(g_WvT + (k4*4+1)*DM + col);
            ulonglong2 b2 = *(const ulonglong2*)(g_WvT + (k4*4+2)*DM + col);
            ulonglong2 b3 = *(const ulonglong2*)(g_WvT + (k4*4+3)*DM + col);
            #pragma unroll
            for (int r = 0; r < 6; r++) {
                ffma2(acc[r][0], dup2(a[r].x), b0.x); ffma2(acc[r][1], dup2(a[r].x), b0.y);
                ffma2(acc[r][0], dup2(a[r].y), b1.x); ffma2(acc[r][1], dup2(a[r].y), b1.y);
                ffma2(acc[r][0], dup2(a[r].z), b2.x); ffma2(acc[r][1], dup2(a[r].z), b2.y);
                ffma2(acc[r][0], dup2(a[r].w), b3.x); ffma2(acc[r][1], dup2(a[r].w), b3.y);
            }
        }
        float4 bv4 = *(const float4*)(bv + col);
        #pragma unroll
        for (int r = 0; r < 6; r++) {
            float lo0, hi0, lo1, hi1;
            unpack2(acc[r][0], lo0, hi0); unpack2(acc[r][1], lo1, hi1);
            float* dst = sm + SM_VP + (j0+r)*TS + col;
            dst[0] = lo0 + bv4.x; dst[1] = hi0 + bv4.y;
            dst[2] = lo1 + bv4.z; dst[3] = hi1 + bv4.w;
        }
    }
    __syncthreads();

    // -------- x_att[r] = P[r,h(c)] @ vproj  -> scratch --------
    {
        const int r    = tid >> 5;          // warp = output row
        const int lane = tid & 31;
        const int col  = lane * 4;
        const int h    = lane >> 2;
        const int p    = r*8 + h;
        ull a01 = 0ull, a23 = 0ull;
        if (r < 2) {
            const float* pr = sm + SM_P + p*SS;
            for (int j = 0; j < NTOK; j++) {
                ull f = dup2(pr[j]);
                ulonglong2 v2 = *(const ulonglong2*)(sm + SM_VP + j*TS + col);
                ffma2(a01, f, v2.x); ffma2(a23, f, v2.y);
            }
        } else {
            const int wi = r - 2;
            const int hw = (wi/3)*4, ww = (wi%3)*2;
            const float* pr = sm + SM_P + p*SS;
            #pragma unroll
            for (int m = 0; m < 8; m++) {
                const int j = (hw + (m>>1))*6 + ww + (m&1);
                ull f = dup2(pr[m]);
                ulonglong2 v2 = *(const ulonglong2*)(sm + SM_VP + j*TS + col);
                ffma2(a01, f, v2.x); ffma2(a23, f, v2.y);
            }
        }
        float4 o;
        unpack2(a01, o.x, o.y); unpack2(a23, o.z, o.w);
        *(float4*)(g_xatt + ((size_t)b*8 + r)*DM + col) = o;
    }
}

// =====================================================================
// Kernel B: GB batches per CTA. Wp + residual + LN + FFN.
// =====================================================================
__device__ __forceinline__ void gemm64(const float* __restrict__ A,
                                       const float* __restrict__ W,
                                       int w, int lane, ull acc[8][2])
{
    const int r0  = w * 8;
    const int col = lane * 4;
    for (int k4 = 0; k4 < 32; k4++) {
        float4 a[8];
        #pragma unroll
        for (int r = 0; r < 8; r++)
            a[r] = *(const float4*)(A + (r0+r)*TS + k4*4);
        ulonglong2 b0 = *(const ulonglong2*)(W + (k4*4+0)*DM + col);
        ulonglong2 b1 = *(const ulonglong2*)(W + (k4*4+1)*DM + col);
        ulonglong2 b2 = *(const ulonglong2*)(W + (k4*4+2)*DM + col);
        ulonglong2 b3 = *(const ulonglong2*)(W + (k4*4+3)*DM + col);
        #pragma unroll
        for (int r = 0; r < 8; r++) {
            ffma2(acc[r][0], dup2(a[r].x), b0.x); ffma2(acc[r][1], dup2(a[r].x), b0.y);
            ffma2(acc[r][0], dup2(a[r].y), b1.x); ffma2(acc[r][1], dup2(a[r].y), b1.y);
            ffma2(acc[r][0], dup2(a[r].z), b2.x); ffma2(acc[r][1], dup2(a[r].z), b2.y);
            ffma2(acc[r][0], dup2(a[r].w), b3.x); ffma2(acc[r][1], dup2(a[r].w), b3.y);
        }
    }
}

__global__ __launch_bounds__(256, 1)
void k_ffn(const float* __restrict__ query, const float* __restrict__ bp,
           const float* __restrict__ g2, const float* __restrict__ b2,
           const float* __restrict__ bf1, const float* __restrict__ bf2,
           float* __restrict__ out, int Bn)
{
    extern __shared__ float sm[];
    const int tid  = threadIdx.x;
    const int w    = tid >> 5;
    const int lane = tid & 31;
    const int col  = lane * 4;
    const int b0   = blockIdx.x * GB;
    const int rows_valid = (Bn - b0 >= GB) ? BROWS : (Bn - b0) * 8;

    // -------- stage x_att tile, WpT, query, consts --------
    {
        const float4* src = (const float4*)(g_xatt + (size_t)b0 * 8 * DM);
        #pragma unroll
        for (int k = 0; k < 8; k++) {
            int i = tid + k*256;           // float4 index over 64x128 tile
            int r = i >> 5, c4 = (i & 31) << 2;
            float4 v = (r < rows_valid) ? src[i] : make_float4(0.f,0.f,0.f,0.f);
            *(float4*)(sm + SMB_XA + r*TS + c4) = v;
        }
        const float4* wsrc = (const float4*)g_WpT;
        float4* wdst = (float4*)(sm + SMB_W);
        #pragma unroll
        for (int k = 0; k < 16; k++) wdst[tid + k*256] = wsrc[tid + k*256];
        ((float4*)(sm + SMB_Q))[tid] = ((const float4*)query)[tid];
        if (tid < 128) {
            sm[SMB_CB +       tid] = bp [tid];
            sm[SMB_CB + 128 + tid] = g2 [tid];
            sm[SMB_CB + 256 + tid] = b2 [tid];
            sm[SMB_CB + 384 + tid] = bf1[tid];
            sm[SMB_CB + 512 + tid] = bf2[tid];
        }
    }
    __syncthreads();

    // -------- GEMM1: x = query + x_att @ WpT + bp --------
    {
        ull acc[8][2] = {};
        gemm64(sm + SMB_XA, sm + SMB_W, w, lane, acc);
        #pragma unroll
        for (int r = 0; r < 8; r++) {
            const int row = w*8 + r;
            float lo0, hi0, lo1, hi1;
            unpack2(acc[r][0], lo0, hi0); unpack2(acc[r][1], lo1, hi1);
            const float* q = sm + SMB_Q + (row & 7)*DM + col;
            const float* bpc = sm + SMB_CB + col;
            float* dst = sm + SMB_X + row*TS + col;
            dst[0] = q[0] + bpc[0] + lo0;
            dst[1] = q[1] + bpc[1] + hi0;
            dst[2] = q[2] + bpc[2] + lo1;
            dst[3] = q[3] + bpc[3] + hi1;
        }
    }
    __syncthreads();

    // -------- LN rows -> s_n ; restage W <- Wf1T --------
    {
        #pragma unroll
        for (int r = 0; r < 8; r++) {
            const int row = w*8 + r;
            const float* xr = sm + SMB_X + row*TS + col;
            float v0 = xr[0], v1 = xr[1], v2 = xr[2], v3 = xr[3];
            float sum = v0+v1+v2+v3;
            float sq  = v0*v0+v1*v1+v2*v2+v3*v3;
            #pragma unroll
            for (int o = 16; o > 0; o >>= 1) {
                sum += __shfl_xor_sync(0xffffffffu, sum, o);
                sq  += __shfl_xor_sync(0xffffffffu, sq,  o);
            }
            float m   = sum * (1.f/DM);
            float var = sq * (1.f/DM) - m*m;
            float rs  = rsqrtf(var + 1e-5f);
            float* nr = sm + SMB_N + row*TS + col;
            const float* g2c = sm + SMB_CB + 128 + col;
            const float* b2c = sm + SMB_CB + 256 + col;
            nr[0] = (v0 - m)*rs*g2c[0] + b2c[0];
            nr[1] = (v1 - m)*rs*g2c[1] + b2c[1];
            nr[2] = (v2 - m)*rs*g2c[2] + b2c[2];
            nr[3] = (v3 - m)*rs*g2c[3] + b2c[3];
        }
        const float4* wsrc = (const float4*)g_Wf1T;
        float4* wdst = (float4*)(sm + SMB_W);
        #pragma unroll
        for (int k = 0; k < 16; k++) wdst[tid + k*256] = wsrc[tid + k*256];
    }
    __syncthreads();

    // -------- GEMM2: h = gelu(xn @ Wf1T + bf1) (overwrite s_n post-sync) --------
    {
        ull acc[8][2] = {};
        gemm64(sm + SMB_N, sm + SMB_W, w, lane, acc);
        __syncthreads();
        #pragma unroll
        for (int r = 0; r < 8; r++) {
            const int row = w*8 + r;
            float z[4];
            unpack2(acc[r][0], z[0], z[1]); unpack2(acc[r][1], z[2], z[3]);
            float* nr = sm + SMB_N + row*TS + col;
            const float* bc = sm + SMB_CB + 384 + col;
            #pragma unroll
            for (int k = 0; k < 4; k++) {
                float zz = z[k] + bc[k];
                nr[k] = 0.5f * zz * (1.f + erff(zz * 0.7071067811865476f));
            }
        }
        const float4* wsrc = (const float4*)g_Wf2T;
        float4* wdst = (float4*)(sm + SMB_W);
        #pragma unroll
        for (int k = 0; k < 16; k++) wdst[tid + k*256] = wsrc[tid + k*256];
    }
    __syncthreads();

    // -------- GEMM3: out = x + h @ Wf2T + bf2 --------
    {
        ull acc[8][2] = {};
        gemm64(sm + SMB_N, sm + SMB_W, w, lane, acc);
        #pragma unroll
        for (int r = 0; r < 8; r++) {
            const int row = w*8 + r;
            if (row >= rows_valid) continue;
            float lo0, hi0, lo1, hi1;
            unpack2(acc[r][0], lo0, hi0); unpack2(acc[r][1], lo1, hi1);
            const float* xr = sm + SMB_X + row*TS + col;
            const float* bc = sm + SMB_CB + 512 + col;
            float4 res;
            res.x = xr[0] + bc[0] + lo0;
            res.y = xr[1] + bc[1] + hi0;
            res.z = xr[2] + bc[2] + lo1;
            res.w = xr[3] + bc[3] + hi1;
            *(float4*)(out + ((size_t)b0*8 + row)*DM + col) = res;
        }
    }
}

// =====================================================================
extern "C" void kernel_launch(void* const* d_in, const int* in_sizes, int n_in,
                              void* d_out, int out_size)
{
    const float* query = (const float*)d_in[0];
    const float* tgt   = (const float*)d_in[1];
    const float* g1    = (const float*)d_in[2];
    const float* b1    = (const float*)d_in[3];
    const float* Wq    = (const float*)d_in[4];
    const float* bq    = (const float*)d_in[5];
    const float* Wk    = (const float*)d_in[6];
    // d_in[7] = bk: drops out (softmax shift invariance)
    const float* Wv    = (const float*)d_in[8];
    const float* bv    = (const float*)d_in[9];
    const float* Wp    = (const float*)d_in[10];
    const float* bp    = (const float*)d_in[11];
    const float* g2    = (const float*)d_in[12];
    const float* b2    = (const float*)d_in[13];
    const float* Wf1   = (const float*)d_in[14];
    const float* bf1   = (const float*)d_in[15];
    const float* Wf2   = (const float*)d_in[16];
    const float* bf2   = (const float*)d_in[17];

    const int B = in_sizes[1] / (NTOK * DM);

    cudaFuncSetAttribute(k_attn, cudaFuncAttributeMaxDynamicSharedMemorySize, A_SMEM_BYTES);
    cudaFuncSetAttribute(k_ffn,  cudaFuncAttributeMaxDynamicSharedMemorySize, B_SMEM_BYTES);

    k_pre<<<1, 256>>>(query, g1, b1, Wq, bq, Wk, Wv, Wp, Wf1, Wf2);
    k_attn<<<B, 256, A_SMEM_BYTES>>>(tgt, bv);
    k_ffn<<<(B + GB - 1)/GB, 256, B_SMEM_BYTES>>>(query, bp, g2, b2, bf1, bf2,
                                                  (float*)d_out, B);
}